// round 15
// baseline (speedup 1.0000x reference)
#include <cuda_runtime.h>
#include <math.h>
#include <stdint.h>

#define BB 2
#define SS 2048
#define DD 1024
#define HH 16
#define HD 64

// Arch-specific gate: tcgen05 is only legal on sm_103a-style targets.
#if defined(__CUDA_ARCH_FEAT_SM103_ALL) || \
    (defined(__CUDA_ARCH_SPECIFIC__) && (__CUDA_ARCH_SPECIFIC__ == 1030))
#define HAS_TC5 1
#else
#define HAS_TC5 0
#endif

// Scratch
__device__ float g_q[BB*HH*SS*HD];
__device__ float g_k[BB*HH*SS*HD];
__device__ float g_v[BB*HH*SS*HD];
__device__ uint32_t g_xt[4096*1024];       // x as tf32 bits, same layout
__device__ uint32_t g_wt[3*1024*1024];     // W^T as tf32 bits: [which][n][k]

// ---------------------------------------------------------------------------
// common helpers
// ---------------------------------------------------------------------------
__device__ __forceinline__ uint32_t f2tf32(float f) {
    uint32_t r;
    asm("cvt.rna.tf32.f32 %0, %1;" : "=r"(r) : "f"(f));
    return r;
}

__device__ __forceinline__ void mma_tf32(float c[4], const uint32_t a[4],
                                         const uint32_t b[2]) {
    asm volatile(
        "mma.sync.aligned.m16n8k8.row.col.f32.tf32.tf32.f32 "
        "{%0,%1,%2,%3}, {%4,%5,%6,%7}, {%8,%9}, {%0,%1,%2,%3};\n"
        : "+f"(c[0]), "+f"(c[1]), "+f"(c[2]), "+f"(c[3])
        : "r"(a[0]), "r"(a[1]), "r"(a[2]), "r"(a[3]),
          "r"(b[0]), "r"(b[1]));
}

__device__ __forceinline__ uint32_t smem_u32(const void* p) {
    uint32_t a;
    asm("{ .reg .u64 t; cvta.to.shared.u64 t, %1; cvt.u32.u64 %0, t; }"
        : "=r"(a) : "l"(p));
    return a;
}

__device__ __forceinline__ void cp16(uint32_t dst, const void* src, int srcsize) {
    asm volatile("cp.async.cg.shared.global [%0], [%1], 16, %2;"
                 :: "r"(dst), "l"(src), "r"(srcsize) : "memory");
}
#define CP_COMMIT() asm volatile("cp.async.commit_group;" ::: "memory")
#define CP_WAIT0()  asm volatile("cp.async.wait_group 0;" ::: "memory")

// ---------------------------------------------------------------------------
// Prep kernels: one-time tf32 conversion (x) and transpose+convert (W).
// ---------------------------------------------------------------------------
__global__ void __launch_bounds__(256)
prep_x(const float* __restrict__ x) {
    const int t = blockIdx.x * 256 + threadIdx.x;     // 1M float4s
    float4 v = reinterpret_cast<const float4*>(x)[t];
    uint4 o;
    o.x = f2tf32(v.x); o.y = f2tf32(v.y);
    o.z = f2tf32(v.z); o.w = f2tf32(v.w);
    reinterpret_cast<uint4*>(g_xt)[t] = o;
}

__global__ void __launch_bounds__(256)
prep_w(const float* __restrict__ Wq, const float* __restrict__ Wk,
       const float* __restrict__ Wv) {
    const int which = blockIdx.z;
    const float* W = (which == 0) ? Wq : (which == 1) ? Wk : Wv;
    __shared__ float t[32][33];
    const int tx = threadIdx.x & 31;
    const int ty = threadIdx.x >> 5;                  // 0..7
    const int k0 = blockIdx.x * 32;
    const int n0 = blockIdx.y * 32;
    #pragma unroll
    for (int i = 0; i < 4; i++) {
        int r = ty + 8 * i;
        t[r][tx] = W[(size_t)(k0 + r) * DD + n0 + tx];
    }
    __syncthreads();
    uint32_t* dst = g_wt + (size_t)which * 1024 * 1024;
    #pragma unroll
    for (int i = 0; i < 4; i++) {
        int r = ty + 8 * i;
        dst[(size_t)(n0 + r) * DD + k0 + tx] = f2tf32(t[tx][r]);
    }
}

#if HAS_TC5
// ---------------------------------------------------------------------------
// tcgen05 helpers
// ---------------------------------------------------------------------------
#define SWZ(off) ((off) ^ (((off) >> 3) & 0x70))
#define DESC_BASE ((2ull << 61) | (1ull << 46) | (64ull << 32) | (1ull << 16))
#define MAKE_DESC(addr) (DESC_BASE | ((uint64_t)((addr) >> 4) & 0x3FFF))
#define IDESC_TF32 ((1u << 4) | (2u << 7) | (2u << 10) | (16u << 17) | (8u << 24))

__device__ __forceinline__ void tcgen05_mma_tf32_ss(uint32_t d_tmem,
                                                    uint64_t a_desc,
                                                    uint64_t b_desc,
                                                    uint32_t enable) {
    asm volatile(
        "{\n\t"
        ".reg .pred p;\n\t"
        "setp.ne.u32 p, %4, 0;\n\t"
        "tcgen05.mma.cta_group::1.kind::tf32 [%0], %1, %2, %3, {%5,%5,%5,%5}, p;\n\t"
        "}"
        :: "r"(d_tmem), "l"(a_desc), "l"(b_desc), "r"(IDESC_TF32),
           "r"(enable), "r"(0u)
        : "memory");
}

#define TC_ALLOC(smem_addr, n) \
    asm volatile("tcgen05.alloc.cta_group::1.sync.aligned.shared::cta.b32 [%0], %1;" \
                 :: "r"(smem_addr), "r"((uint32_t)(n)) : "memory")
#define TC_DEALLOC(tmem, n) \
    asm volatile("tcgen05.dealloc.cta_group::1.sync.aligned.b32 %0, %1;" \
                 :: "r"(tmem), "r"((uint32_t)(n)))
#define TC_RELINQ() \
    asm volatile("tcgen05.relinquish_alloc_permit.cta_group::1.sync.aligned;")
#define TC_COMMIT(mbar) \
    asm volatile("tcgen05.commit.cta_group::1.mbarrier::arrive::one.shared::cluster.b64 [%0];" \
                 :: "r"(mbar) : "memory")
#define TC_FENCE_AFTER() \
    asm volatile("tcgen05.fence::after_thread_sync;" ::: "memory")
#define TC_WAIT_LD() \
    asm volatile("tcgen05.wait::ld.sync.aligned;" ::: "memory")
#define FENCE_ASYNC() \
    asm volatile("fence.proxy.async.shared::cta;" ::: "memory")
#define MBAR_INIT(mbar, cnt) \
    asm volatile("mbarrier.init.shared.b64 [%0], %1;" :: "r"(mbar), "r"((uint32_t)(cnt)) : "memory")

__device__ __forceinline__ void mbar_wait(uint32_t mbar, uint32_t parity) {
    asm volatile(
        "{\n\t"
        ".reg .pred P1;\n\t"
        "WAIT_%=:\n\t"
        "mbarrier.try_wait.parity.shared::cta.b64 P1, [%0], %1, 0x989680;\n\t"
        "@P1 bra.uni DONE_%=;\n\t"
        "bra.uni WAIT_%=;\n\t"
        "DONE_%=:\n\t"
        "}"
        :: "r"(mbar), "r"(parity) : "memory");
}

#define TC_LD_X32(r, tmem) \
    asm volatile( \
        "tcgen05.ld.sync.aligned.32x32b.x32.b32 " \
        "{%0, %1, %2, %3, %4, %5, %6, %7, " \
        " %8, %9, %10, %11, %12, %13, %14, %15, " \
        " %16, %17, %18, %19, %20, %21, %22, %23, " \
        " %24, %25, %26, %27, %28, %29, %30, %31}, [%32];" \
        : "=r"((r)[0]),  "=r"((r)[1]),  "=r"((r)[2]),  "=r"((r)[3]), \
          "=r"((r)[4]),  "=r"((r)[5]),  "=r"((r)[6]),  "=r"((r)[7]), \
          "=r"((r)[8]),  "=r"((r)[9]),  "=r"((r)[10]), "=r"((r)[11]), \
          "=r"((r)[12]), "=r"((r)[13]), "=r"((r)[14]), "=r"((r)[15]), \
          "=r"((r)[16]), "=r"((r)[17]), "=r"((r)[18]), "=r"((r)[19]), \
          "=r"((r)[20]), "=r"((r)[21]), "=r"((r)[22]), "=r"((r)[23]), \
          "=r"((r)[24]), "=r"((r)[25]), "=r"((r)[26]), "=r"((r)[27]), \
          "=r"((r)[28]), "=r"((r)[29]), "=r"((r)[30]), "=r"((r)[31]) \
        : "r"(tmem))
#endif  // HAS_TC5

// ---------------------------------------------------------------------------
// QKV projection. tcgen05 path: cp.async-pipelined staging from pre-converted
// g_xt / g_wt (both K-major, 128B chunks, swizzle-compatible). Fallback: R6.
// ---------------------------------------------------------------------------
#define GSM_A0 1024
#define GSM_A1 17408
#define GSM_B0 33792
#define GSM_B1 50176
#define GSM_TOTAL 66560
#define NCHUNK 32
#define TMEM_COLS 128
#define LDW 136

__global__ void __launch_bounds__(256)
qkv_gemm_tc(const float* __restrict__ x, const float* __restrict__ W,
            const float* __restrict__ bias, int which) {
    float* out = (which == 0) ? g_q : (which == 1) ? g_k : g_v;

    extern __shared__ char smg[];
    const int tid  = threadIdx.x;
    const int lane = tid & 31;
    const int warp = tid >> 5;
    const int row0 = blockIdx.x * 128;
    const int col0 = blockIdx.y * 128;

#if HAS_TC5
    const uint32_t smem_base = smem_u32(smg);
    const uint32_t mbar0 = smem_base + 8;
    const uint32_t mbar1 = smem_base + 16;

    if (warp == 0) {
        TC_ALLOC(smem_base, TMEM_COLS);
        TC_RELINQ();
    }
    if (tid == 0) {
        MBAR_INIT(mbar0, 1);
        MBAR_INIT(mbar1, 1);
    }
    __syncthreads();
    uint32_t tmem;
    asm volatile("ld.shared.b32 %0, [%1];" : "=r"(tmem) : "r"(smem_base));

    const uint32_t* xt = g_xt;
    const uint32_t* wt = g_wt + (size_t)which * 1024 * 1024;

    const int ar = tid >> 1;               // tile row 0..127
    const int hb = (tid & 1) * 16;         // 16-float (64B) half offset

    // stage chunk c into buffer bsel via cp.async (A: x rows, B: W^T rows)
    auto stage = [&](int c, int bsel) {
        const uint32_t abase = smem_base + (bsel ? GSM_A1 : GSM_A0);
        const uint32_t bbase = smem_base + (bsel ? GSM_B1 : GSM_B0);
        const uint32_t rb = (uint32_t)(ar * 128 + hb * 4);
        const uint32_t* asrc = xt + (size_t)(row0 + ar) * DD + c * 32 + hb;
        const uint32_t* bsrc = wt + (size_t)(col0 + ar) * DD + c * 32 + hb;
        #pragma unroll
        for (int u = 0; u < 4; u++) {
            cp16(abase + SWZ(rb + u * 16), asrc + u * 4, 16);
            cp16(bbase + SWZ(rb + u * 16), bsrc + u * 4, 16);
        }
    };

    int ph[2] = {0, 0};

    stage(0, 0);
    CP_COMMIT();

    for (int c = 0; c < NCHUNK; c++) {
        const int buf = c & 1;
        const uint32_t aoff = buf ? GSM_A1 : GSM_A0;
        const uint32_t boff = buf ? GSM_B1 : GSM_B0;

        CP_WAIT0();
        FENCE_ASYNC();
        __syncthreads();

        if (tid == 0) {
            uint64_t ad = MAKE_DESC(smem_base + aoff);
            uint64_t bd = MAKE_DESC(smem_base + boff);
            #pragma unroll
            for (int s = 0; s < 4; s++)
                tcgen05_mma_tf32_ss(tmem, ad + s * 2, bd + s * 2,
                                    (c > 0 || s > 0) ? 1u : 0u);
            TC_COMMIT(buf == 0 ? mbar0 : mbar1);
        }

        if (c < NCHUNK - 1) {
            // before overwriting buf^1: chunk c-1's mma (same buffer) must be done
            if (c >= 1) {
                mbar_wait(buf ? mbar0 : mbar1, ph[buf ^ 1]);
                ph[buf ^ 1] ^= 1;
            }
            stage(c + 1, buf ^ 1);
            CP_COMMIT();
        }
    }

    mbar_wait(mbar0, ph[0]);
    mbar_wait(mbar1, ph[1]);
    __syncthreads();

    if (warp < 4) {
        TC_FENCE_AFTER();
        const int row = row0 + warp * 32 + lane;
        const int b_ = row >> 11;
        const int s_ = row & 2047;
        float* obase = out + (size_t)(b_ * HH) * SS * HD + (size_t)s_ * HD;
        #pragma unroll
        for (int nb = 0; nb < 4; nb++) {
            uint32_t d_regs[32];
            TC_LD_X32(d_regs, tmem + nb * 32);
            TC_WAIT_LD();
            #pragma unroll
            for (int c4 = 0; c4 < 8; c4++) {
                const int col = col0 + nb * 32 + c4 * 4;
                const int h_ = col >> 6;
                const int d_ = col & 63;
                float4 bb = *reinterpret_cast<const float4*>(&bias[col]);
                float4 r;
                r.x = __uint_as_float(d_regs[c4 * 4 + 0]) + bb.x;
                r.y = __uint_as_float(d_regs[c4 * 4 + 1]) + bb.y;
                r.z = __uint_as_float(d_regs[c4 * 4 + 2]) + bb.z;
                r.w = __uint_as_float(d_regs[c4 * 4 + 3]) + bb.w;
                *reinterpret_cast<float4*>(&obase[(size_t)h_ * SS * HD + d_]) = r;
            }
        }
    }
    __syncthreads();
    if (warp == 0) TC_DEALLOC(tmem, TMEM_COLS);

#else
    // mma.sync fallback (R6, proven; uses raw x/W — prep arrays unused)
    uint32_t* As = reinterpret_cast<uint32_t*>(smg);
    uint32_t* Bs = As + 2 * 16 * LDW;

    const int wm = (warp & 1) * 64;
    const int wn = (warp >> 1) * 32;
    const int tig = lane & 3;
    const int grp = lane >> 2;

    float c[4][4][4];
    #pragma unroll
    for (int mt = 0; mt < 4; mt++)
        #pragma unroll
        for (int nt = 0; nt < 4; nt++)
            #pragma unroll
            for (int r = 0; r < 4; r++) c[mt][nt][r] = 0.f;

    float4 xa[2], wv[2];

    #pragma unroll
    for (int i = 0; i < 2; i++) {
        int idx = tid + i * 256;
        int arr = idx >> 2, akq = (idx & 3) * 4;
        xa[i] = *reinterpret_cast<const float4*>(&x[(size_t)(row0 + arr) * DD + akq]);
        int bkk = idx >> 5, bcc = (idx & 31) * 4;
        wv[i] = *reinterpret_cast<const float4*>(&W[(size_t)bkk * DD + col0 + bcc]);
    }
    #pragma unroll
    for (int i = 0; i < 2; i++) {
        int idx = tid + i * 256;
        int arr = idx >> 2, akq = (idx & 3) * 4;
        As[(akq + 0) * LDW + arr] = f2tf32(xa[i].x);
        As[(akq + 1) * LDW + arr] = f2tf32(xa[i].y);
        As[(akq + 2) * LDW + arr] = f2tf32(xa[i].z);
        As[(akq + 3) * LDW + arr] = f2tf32(xa[i].w);
        int bkk = idx >> 5, bcc = (idx & 31) * 4;
        uint4 wt2;
        wt2.x = f2tf32(wv[i].x); wt2.y = f2tf32(wv[i].y);
        wt2.z = f2tf32(wv[i].z); wt2.w = f2tf32(wv[i].w);
        *reinterpret_cast<uint4*>(&Bs[bkk * LDW + bcc]) = wt2;
    }
    __syncthreads();

    for (int kt = 0; kt < 64; kt++) {
        const int buf = kt & 1;
        uint32_t* Ab = As + buf * 16 * LDW;
        uint32_t* Bb = Bs + buf * 16 * LDW;

        if (kt < 63) {
            const int k0 = (kt + 1) * 16;
            #pragma unroll
            for (int i = 0; i < 2; i++) {
                int idx = tid + i * 256;
                int arr = idx >> 2, akq = (idx & 3) * 4;
                xa[i] = *reinterpret_cast<const float4*>(
                    &x[(size_t)(row0 + arr) * DD + k0 + akq]);
                int bkk = idx >> 5, bcc = (idx & 31) * 4;
                wv[i] = *reinterpret_cast<const float4*>(
                    &W[(size_t)(k0 + bkk) * DD + col0 + bcc]);
            }
        }

        #pragma unroll
        for (int ks = 0; ks < 16; ks += 8) {
            const int ak = ks + tig;
            uint32_t a[4][4], b[4][2];
            #pragma unroll
            for (int mt = 0; mt < 4; mt++) {
                int r = wm + mt * 16 + grp;
                a[mt][0] = Ab[ak * LDW + r];
                a[mt][1] = Ab[ak * LDW + r + 8];
                a[mt][2] = Ab[(ak + 4) * LDW + r];
                a[mt][3] = Ab[(ak + 4) * LDW + r + 8];
            }
            #pragma unroll
            for (int nt = 0; nt < 4; nt++) {
                int n = wn + nt * 8 + grp;
                b[nt][0] = Bb[ak * LDW + n];
                b[nt][1] = Bb[(ak + 4) * LDW + n];
            }
            #pragma unroll
            for (int mt = 0; mt < 4; mt++)
                #pragma unroll
                for (int nt = 0; nt < 4; nt++)
                    mma_tf32(c[mt][nt], a[mt], b[nt]);
        }

        if (kt < 63) {
            const int nb = buf ^ 1;
            uint32_t* An = As + nb * 16 * LDW;
            uint32_t* Bn = Bs + nb * 16 * LDW;
            #pragma unroll
            for (int i = 0; i < 2; i++) {
                int idx = tid + i * 256;
                int arr = idx >> 2, akq = (idx & 3) * 4;
                An[(akq + 0) * LDW + arr] = f2tf32(xa[i].x);
                An[(akq + 1) * LDW + arr] = f2tf32(xa[i].y);
                An[(akq + 2) * LDW + arr] = f2tf32(xa[i].z);
                An[(akq + 3) * LDW + arr] = f2tf32(xa[i].w);
                int bkk = idx >> 5, bcc = (idx & 31) * 4;
                uint4 wt2;
                wt2.x = f2tf32(wv[i].x); wt2.y = f2tf32(wv[i].y);
                wt2.z = f2tf32(wv[i].z); wt2.w = f2tf32(wv[i].w);
                *reinterpret_cast<uint4*>(&Bn[bkk * LDW + bcc]) = wt2;
            }
        }
        __syncthreads();
    }

    #pragma unroll
    for (int nt = 0; nt < 4; nt++) {
        const int col = col0 + wn + nt * 8 + tig * 2;
        const int h_ = col >> 6;
        const int d_ = col & 63;
        const float2 bb = *reinterpret_cast<const float2*>(&bias[col]);
        #pragma unroll
        for (int mt = 0; mt < 4; mt++) {
            int rowa = row0 + wm + mt * 16 + grp;
            #pragma unroll
            for (int half = 0; half < 2; half++) {
                int row = rowa + half * 8;
                int b_ = row >> 11;
                int s_ = row & 2047;
                float2 rv;
                rv.x = c[mt][nt][half * 2 + 0] + bb.x;
                rv.y = c[mt][nt][half * 2 + 1] + bb.y;
                *reinterpret_cast<float2*>(
                    &out[((size_t)((b_ * HH + h_) * SS) + s_) * HD + d_]) = rv;
            }
        }
    }
#endif
}

// ---------------------------------------------------------------------------
// tf32-mma flash block-sparse attention (R13, unchanged).
// ---------------------------------------------------------------------------
#define PADK 68
#define PADV 72
#define A_K0 0
#define A_K1 (64*PADK)
#define A_V0 (2*64*PADK)
#define A_V1 (2*64*PADK + 64*PADV)
#define A_KPM (2*64*PADK + 2*64*PADV)
#define A_FLOATS (A_KPM + 128)

__global__ void __launch_bounds__(128, 3)
sparse_attn_kernel(const float* __restrict__ kpm, float* __restrict__ out) {
    extern __shared__ float smf[];
    const uint32_t smem_base = smem_u32(smf);

    const int w = 31 - blockIdx.x;
    const int h = blockIdx.y;
    const int b = blockIdx.z;

    const int tid  = threadIdx.x;
    const int lane = tid & 31;
    const int warp = tid >> 5;
    const int wq   = warp * 16;
    const int grp  = lane >> 2;
    const int tig  = lane & 3;

    const size_t head_base = (size_t)(b * HH + h) * SS * HD;
    const int row_a = wq + grp;
    const int row_b = wq + grp + 8;
    const int nkt = (w + 3) >> 2;

    auto stage_tile = [&](int it, int bsel) {
        const uint32_t kbase = smem_base + (bsel ? A_K1 : A_K0) * 4;
        const uint32_t vbase = smem_base + (bsel ? A_V1 : A_V0) * 4;
        const bool isWinT = (it == nkt);
        #pragma unroll
        for (int j = 0; j < 8; j++) {
            int cch = tid + 128 * j;
            int r = cch >> 4;
            int c4 = (cch & 15) * 4;
            int sub = r >> 4, rr = r & 15;
            int kb, vsz;
            if (isWinT) { kb = 4 * w + sub; vsz = 16; }
            else {
                int g = it * 4 + sub;
                kb = (g < w) ? 4 * g + 3 : 3;
                vsz = (g < w) ? 16 : 0;
            }
            const float* ks = g_k + head_base + (size_t)(kb * 16 + rr) * HD + c4;
            const float* vs = g_v + head_base + (size_t)(kb * 16 + rr) * HD + c4;
            cp16(kbase + (uint32_t)(r * PADK + c4) * 4, ks, vsz);
            cp16(vbase + (uint32_t)(r * PADV + c4) * 4, vs, vsz);
        }
    };

    auto convert_tile = [&](int bsel) {
        float* Kb = smf + (bsel ? A_K1 : A_K0);
        float* Vb = smf + (bsel ? A_V1 : A_V0);
        #pragma unroll
        for (int j = 0; j < 8; j++) {
            int cch = tid + 128 * j;
            int r = cch >> 4;
            int c4 = (cch & 15) * 4;
            float4 kv = *reinterpret_cast<const float4*>(&Kb[r * PADK + c4]);
            uint4 kt;
            kt.x = f2tf32(kv.x); kt.y = f2tf32(kv.y);
            kt.z = f2tf32(kv.z); kt.w = f2tf32(kv.w);
            *reinterpret_cast<uint4*>(&Kb[r * PADK + c4]) = kt;
            float4 vv = *reinterpret_cast<const float4*>(&Vb[r * PADV + c4]);
            uint4 vt;
            vt.x = f2tf32(vv.x); vt.y = f2tf32(vv.y);
            vt.z = f2tf32(vv.z); vt.w = f2tf32(vv.w);
            *reinterpret_cast<uint4*>(&Vb[r * PADV + c4]) = vt;
        }
    };

    auto kpm_load = [&](int it) -> float {
        if (tid >= 64) return 0.f;
        const bool isWinT = (it == nkt);
        int kb; bool v2;
        if (isWinT) { kb = 4 * w + (tid >> 4); v2 = true; }
        else {
            int g = it * 4 + (tid >> 4);
            v2 = (g < w);
            kb = 4 * g + 3;
        }
        return v2 ? kpm[b * SS + kb * 16 + (tid & 15)] : -INFINITY;
    };

    uint32_t qa[8][4];
    {
        const float* qra = g_q + head_base + (size_t)(w * 64 + row_a) * HD;
        const float* qrb = g_q + head_base + (size_t)(w * 64 + row_b) * HD;
        #pragma unroll
        for (int ks = 0; ks < 8; ks++) {
            qa[ks][0] = f2tf32(qra[ks * 8 + tig]);
            qa[ks][1] = f2tf32(qrb[ks * 8 + tig]);
            qa[ks][2] = f2tf32(qra[ks * 8 + tig + 4]);
            qa[ks][3] = f2tf32(qrb[ks * 8 + tig + 4]);
        }
    }

    float o[8][4];
    #pragma unroll
    for (int nt = 0; nt < 8; nt++)
        #pragma unroll
        for (int r = 0; r < 4; r++) o[nt][r] = 0.f;
    float m0 = -1e30f, m1 = -1e30f, l0 = 0.f, l1 = 0.f;
    const float scale = 0.125f;

    stage_tile(0, 0);
    CP_COMMIT();
    float kpm_reg = kpm_load(0);

    for (int it = 0; it <= nkt; it++) {
        const int buf = it & 1;
        const uint32_t* Kb = reinterpret_cast<const uint32_t*>(smf + (buf ? A_K1 : A_K0));
        const uint32_t* Vb = reinterpret_cast<const uint32_t*>(smf + (buf ? A_V1 : A_V0));
        float* kpms = smf + A_KPM + buf * 64;
        const bool isWin = (it == nkt);

        CP_WAIT0();
        convert_tile(buf);
        if (tid < 64) kpms[tid] = kpm_reg;
        __syncthreads();

        if (it < nkt) {
            stage_tile(it + 1, buf ^ 1);
            CP_COMMIT();
            kpm_reg = kpm_load(it + 1);
        }

        float sc[8][4];
        #pragma unroll
        for (int nt = 0; nt < 8; nt++)
            #pragma unroll
            for (int r = 0; r < 4; r++) sc[nt][r] = 0.f;

        #pragma unroll
        for (int ks = 0; ks < 8; ks++) {
            #pragma unroll
            for (int nt = 0; nt < 8; nt++) {
                uint32_t bfr[2];
                bfr[0] = Kb[(nt * 8 + grp) * PADK + ks * 8 + tig];
                bfr[1] = Kb[(nt * 8 + grp) * PADK + ks * 8 + tig + 4];
                mma_tf32(sc[nt], qa[ks], bfr);
            }
        }

        #pragma unroll
        for (int nt = 0; nt < 8; nt++) {
            #pragma unroll
            for (int cc = 0; cc < 2; cc++) {
                int col = nt * 8 + tig * 2 + cc;
                float kv = kpms[col];
                float v0 = sc[nt][cc]     * scale + kv;
                float v1 = sc[nt][2 + cc] * scale + kv;
                if (isWin) {
                    if ((col >> 4) > (row_a >> 4)) v0 = -INFINITY;
                    if ((col >> 4) > (row_b >> 4)) v1 = -INFINITY;
                }
                sc[nt][cc] = v0;
                sc[nt][2 + cc] = v1;
            }
        }

        float mx0 = -INFINITY, mx1 = -INFINITY;
        #pragma unroll
        for (int nt = 0; nt < 8; nt++) {
            mx0 = fmaxf(mx0, fmaxf(sc[nt][0], sc[nt][1]));
            mx1 = fmaxf(mx1, fmaxf(sc[nt][2], sc[nt][3]));
        }
        mx0 = fmaxf(mx0, __shfl_xor_sync(0xffffffffu, mx0, 1));
        mx0 = fmaxf(mx0, __shfl_xor_sync(0xffffffffu, mx0, 2));
        mx1 = fmaxf(mx1, __shfl_xor_sync(0xffffffffu, mx1, 1));
        mx1 = fmaxf(mx1, __shfl_xor_sync(0xffffffffu, mx1, 2));

        const float nm0 = fmaxf(m0, mx0);
        const float nm1 = fmaxf(m1, mx1);
        const float al0 = __expf(m0 - nm0);
        const float al1 = __expf(m1 - nm1);
        m0 = nm0; m1 = nm1;

        float rs0 = 0.f, rs1 = 0.f;
        #pragma unroll
        for (int nt = 0; nt < 8; nt++) {
            #pragma unroll
            for (int cc = 0; cc < 2; cc++) {
                float p0 = __expf(sc[nt][cc] - nm0);
                float p1 = __expf(sc[nt][2 + cc] - nm1);
                sc[nt][cc] = p0;
                sc[nt][2 + cc] = p1;
                rs0 += p0; rs1 += p1;
            }
        }
        rs0 += __shfl_xor_sync(0xffffffffu, rs0, 1);
        rs0 += __shfl_xor_sync(0xffffffffu, rs0, 2);
        rs1 += __shfl_xor_sync(0xffffffffu, rs1, 1);
        rs1 += __shfl_xor_sync(0xffffffffu, rs1, 2);
        l0 = l0 * al0 + rs0;
        l1 = l1 * al1 + rs1;
        #pragma unroll
        for (int nt = 0; nt < 8; nt++) {
            o[nt][0] *= al0; o[nt][1] *= al0;
            o[nt][2] *= al1; o[nt][3] *= al1;
        }

        __syncthreads();

        uint32_t* Pb = const_cast<uint32_t*>(Kb);
        #pragma unroll
        for (int nt = 0; nt < 8; nt++) {
            uint2 p0, p1;
            p0.x = f2tf32(sc[nt][0]); p0.y = f2tf32(sc[nt][1]);
            p1.x = f2tf32(sc[nt][2]); p1.y = f2tf32(sc[nt][3]);
            *reinterpret_cast<uint2*>(&Pb[row_a * PADK + nt * 8 + tig * 2]) = p0;
            *reinterpret_cast<uint2*>(&Pb[row_b * PADK + nt * 8 + tig * 2]) = p1;
        }
        __syncwarp();

        #pragma unroll
        for (int ks = 0; ks < 8; ks++) {
            uint32_t a[4];
            a[0] = Pb[row_a * PADK + ks * 8 + tig];
            a[1] = Pb[row_b * PADK + ks * 8 + tig];
            a[2] = Pb[row_a * PADK + ks * 8 + tig + 4];
            a[3] = Pb[row_b * PADK + ks * 8 + tig + 4];
            #pragma unroll
            for (int nt = 0; nt < 8; nt++) {
                uint32_t bfr[2];
                bfr[0] = Vb[(ks * 8 + tig) * PADV + nt * 8 + grp];
                bfr[1] = Vb[(ks * 8 + tig + 4) * PADV + nt * 8 + grp];
                mma_tf32(o[nt], a, bfr);
            }
        }
    }

    const float inv0 = 1.f / l0;
    const float inv1 = 1.f / l1;
    #pragma unroll
    for (int nt = 0; nt < 8; nt++) {
        int d_ = nt * 8 + tig * 2;
        float2 r0, r1;
        r0.x = o[nt][0] * inv0; r0.y = o[nt][1] * inv0;
        r1.x = o[nt][2] * inv1; r1.y = o[nt][3] * inv1;
        *reinterpret_cast<float2*>(
            &out[(size_t)(b * SS + w * 64 + row_a) * DD + h * HD + d_]) = r0;
        *reinterpret_cast<float2*>(
            &out[(size_t)(b * SS + w * 64 + row_b) * DD + h * HD + d_]) = r1;
    }
}

// ---------------------------------------------------------------------------
// Launch
// ---------------------------------------------------------------------------
extern "C" void kernel_launch(void* const* d_in, const int* in_sizes, int n_in,
                              void* d_out, int out_size) {
    const float* x   = (const float*)d_in[0];
    const float* kpm = (const float*)d_in[1];
    const float* Wq  = (const float*)d_in[2];
    const float* bq  = (const float*)d_in[3];
    const float* Wk  = (const float*)d_in[4];
    const float* bk  = (const float*)d_in[5];
    const float* Wv  = (const float*)d_in[6];
    const float* bv  = (const float*)d_in[7];
    float* out = (float*)d_out;

    static int smem_set = 0;
    const int attn_smem = A_FLOATS * sizeof(float);   // 72192
    if (!smem_set) {
        cudaFuncSetAttribute(sparse_attn_kernel,
                             cudaFuncAttributeMaxDynamicSharedMemorySize,
                             attn_smem);
        cudaFuncSetAttribute(qkv_gemm_tc,
                             cudaFuncAttributeMaxDynamicSharedMemorySize,
                             GSM_TOTAL);
        smem_set = 1;
    }

    prep_x<<<4096, 256>>>(x);
    dim3 wgrid(32, 32, 3);
    prep_w<<<wgrid, 256>>>(Wq, Wk, Wv);

    dim3 ggrid(32, 8);
    qkv_gemm_tc<<<ggrid, 256, GSM_TOTAL>>>(x, Wq, bq, 0);
    qkv_gemm_tc<<<ggrid, 256, GSM_TOTAL>>>(x, Wk, bk, 1);
    qkv_gemm_tc<<<ggrid, 256, GSM_TOTAL>>>(x, Wv, bv, 2);

    dim3 agrid(32, HH, BB);
    sparse_attn_kernel<<<agrid, 128, attn_smem>>>(kpm, out);
}

// round 16
// speedup vs baseline: 1.6113x; 1.6113x over previous
#include <cuda_runtime.h>
#include <math.h>
#include <stdint.h>

#define BB 2
#define SS 2048
#define DD 1024
#define HH 16
#define HD 64

// Arch-specific gate: tcgen05 is only legal on sm_103a-style targets.
#if defined(__CUDA_ARCH_FEAT_SM103_ALL) || \
    (defined(__CUDA_ARCH_SPECIFIC__) && (__CUDA_ARCH_SPECIFIC__ == 1030))
#define HAS_TC5 1
#else
#define HAS_TC5 0
#endif

// Scratch: q,k,v in [b][h][s][d] layout.
__device__ float g_q[BB*HH*SS*HD];
__device__ float g_k[BB*HH*SS*HD];
__device__ float g_v[BB*HH*SS*HD];

// ---------------------------------------------------------------------------
// common helpers
// ---------------------------------------------------------------------------
__device__ __forceinline__ uint32_t f2tf32(float f) {
    uint32_t r;
    asm("cvt.rna.tf32.f32 %0, %1;" : "=r"(r) : "f"(f));
    return r;
}

__device__ __forceinline__ void mma_tf32(float c[4], const uint32_t a[4],
                                         const uint32_t b[2]) {
    asm volatile(
        "mma.sync.aligned.m16n8k8.row.col.f32.tf32.tf32.f32 "
        "{%0,%1,%2,%3}, {%4,%5,%6,%7}, {%8,%9}, {%0,%1,%2,%3};\n"
        : "+f"(c[0]), "+f"(c[1]), "+f"(c[2]), "+f"(c[3])
        : "r"(a[0]), "r"(a[1]), "r"(a[2]), "r"(a[3]),
          "r"(b[0]), "r"(b[1]));
}

__device__ __forceinline__ uint32_t smem_u32(const void* p) {
    uint32_t a;
    asm("{ .reg .u64 t; cvta.to.shared.u64 t, %1; cvt.u32.u64 %0, t; }"
        : "=r"(a) : "l"(p));
    return a;
}

// cp.async 16B with runtime src-size (0 => zero-fill)
__device__ __forceinline__ void cp16(uint32_t dst, const void* src, int srcsize) {
    asm volatile("cp.async.cg.shared.global [%0], [%1], 16, %2;"
                 :: "r"(dst), "l"(src), "r"(srcsize) : "memory");
}
#define CP_COMMIT() asm volatile("cp.async.commit_group;" ::: "memory")
#define CP_WAIT0()  asm volatile("cp.async.wait_group 0;" ::: "memory")

#if HAS_TC5
// ---------------------------------------------------------------------------
// tcgen05 helpers
// ---------------------------------------------------------------------------
#define SWZ(off) ((off) ^ (((off) >> 3) & 0x70))
#define DESC_BASE ((2ull << 61) | (1ull << 46) | (64ull << 32) | (1ull << 16))
#define MAKE_DESC(addr) (DESC_BASE | ((uint64_t)((addr) >> 4) & 0x3FFF))
#define IDESC_TF32 ((1u << 4) | (2u << 7) | (2u << 10) | (16u << 17) | (8u << 24))

__device__ __forceinline__ void tcgen05_mma_tf32_ss(uint32_t d_tmem,
                                                    uint64_t a_desc,
                                                    uint64_t b_desc,
                                                    uint32_t enable) {
    asm volatile(
        "{\n\t"
        ".reg .pred p;\n\t"
        "setp.ne.u32 p, %4, 0;\n\t"
        "tcgen05.mma.cta_group::1.kind::tf32 [%0], %1, %2, %3, {%5,%5,%5,%5}, p;\n\t"
        "}"
        :: "r"(d_tmem), "l"(a_desc), "l"(b_desc), "r"(IDESC_TF32),
           "r"(enable), "r"(0u)
        : "memory");
}

#define TC_ALLOC(smem_addr, n) \
    asm volatile("tcgen05.alloc.cta_group::1.sync.aligned.shared::cta.b32 [%0], %1;" \
                 :: "r"(smem_addr), "r"((uint32_t)(n)) : "memory")
#define TC_DEALLOC(tmem, n) \
    asm volatile("tcgen05.dealloc.cta_group::1.sync.aligned.b32 %0, %1;" \
                 :: "r"(tmem), "r"((uint32_t)(n)))
#define TC_RELINQ() \
    asm volatile("tcgen05.relinquish_alloc_permit.cta_group::1.sync.aligned;")
#define TC_COMMIT(mbar) \
    asm volatile("tcgen05.commit.cta_group::1.mbarrier::arrive::one.shared::cluster.b64 [%0];" \
                 :: "r"(mbar) : "memory")
#define TC_FENCE_AFTER() \
    asm volatile("tcgen05.fence::after_thread_sync;" ::: "memory")
#define TC_WAIT_LD() \
    asm volatile("tcgen05.wait::ld.sync.aligned;" ::: "memory")
#define FENCE_ASYNC() \
    asm volatile("fence.proxy.async.shared::cta;" ::: "memory")
#define MBAR_INIT(mbar, cnt) \
    asm volatile("mbarrier.init.shared.b64 [%0], %1;" :: "r"(mbar), "r"((uint32_t)(cnt)) : "memory")

__device__ __forceinline__ void mbar_wait(uint32_t mbar, uint32_t parity) {
    asm volatile(
        "{\n\t"
        ".reg .pred P1;\n\t"
        "WAIT_%=:\n\t"
        "mbarrier.try_wait.parity.shared::cta.b64 P1, [%0], %1, 0x989680;\n\t"
        "@P1 bra.uni DONE_%=;\n\t"
        "bra.uni WAIT_%=;\n\t"
        "DONE_%=:\n\t"
        "}"
        :: "r"(mbar), "r"(parity) : "memory");
}

#define TC_LD_X32(r, tmem) \
    asm volatile( \
        "tcgen05.ld.sync.aligned.32x32b.x32.b32 " \
        "{%0, %1, %2, %3, %4, %5, %6, %7, " \
        " %8, %9, %10, %11, %12, %13, %14, %15, " \
        " %16, %17, %18, %19, %20, %21, %22, %23, " \
        " %24, %25, %26, %27, %28, %29, %30, %31}, [%32];" \
        : "=r"((r)[0]),  "=r"((r)[1]),  "=r"((r)[2]),  "=r"((r)[3]), \
          "=r"((r)[4]),  "=r"((r)[5]),  "=r"((r)[6]),  "=r"((r)[7]), \
          "=r"((r)[8]),  "=r"((r)[9]),  "=r"((r)[10]), "=r"((r)[11]), \
          "=r"((r)[12]), "=r"((r)[13]), "=r"((r)[14]), "=r"((r)[15]), \
          "=r"((r)[16]), "=r"((r)[17]), "=r"((r)[18]), "=r"((r)[19]), \
          "=r"((r)[20]), "=r"((r)[21]), "=r"((r)[22]), "=r"((r)[23]), \
          "=r"((r)[24]), "=r"((r)[25]), "=r"((r)[26]), "=r"((r)[27]), \
          "=r"((r)[28]), "=r"((r)[29]), "=r"((r)[30]), "=r"((r)[31]) \
        : "r"(tmem))
#endif  // HAS_TC5

// ---------------------------------------------------------------------------
// QKV projection. tcgen05 path (R12 staging) + one-chunk REGISTER PREFETCH:
// LDG for chunk c+1 issues right after chunk c's STS, hiding global latency
// behind fence+sync+mma+next mbar_wait. Fallback: R6 mma.sync (proven).
// ---------------------------------------------------------------------------
#define GSM_A0 1024
#define GSM_A1 17408
#define GSM_B0 33792
#define GSM_B1 50176
#define GSM_TOTAL 66560
#define NCHUNK 32
#define TMEM_COLS 128
#define LDW 136

__global__ void __launch_bounds__(256)
qkv_gemm_tc(const float* __restrict__ x, const float* __restrict__ W,
            const float* __restrict__ bias, int which) {
    float* out = (which == 0) ? g_q : (which == 1) ? g_k : g_v;

    extern __shared__ char smg[];
    const int tid  = threadIdx.x;
    const int lane = tid & 31;
    const int warp = tid >> 5;
    const int row0 = blockIdx.x * 128;
    const int col0 = blockIdx.y * 128;

#if HAS_TC5
    const uint32_t smem_base = smem_u32(smg);
    const uint32_t mbar0 = smem_base + 8;
    const uint32_t mbar1 = smem_base + 16;

    if (warp == 0) {
        TC_ALLOC(smem_base, TMEM_COLS);
        TC_RELINQ();
    }
    if (tid == 0) {
        MBAR_INIT(mbar0, 1);
        MBAR_INIT(mbar1, 1);
    }
    __syncthreads();
    uint32_t tmem;
    asm volatile("ld.shared.b32 %0, [%1];" : "=r"(tmem) : "r"(smem_base));

    const int ar  = tid >> 1;             // A row (M)
    const int acb = (tid & 1) * 16;       // A col base (K floats)

    float4 xa[4];        // A chunk: 16 floats
    float4 wb[4];        // B chunk: 4 tasks x 4 floats

    auto ldg_chunk = [&](int c) {
        const float* asrc = x + (size_t)(row0 + ar) * DD + c * 32 + acb;
        #pragma unroll
        for (int u = 0; u < 4; u++)
            xa[u] = *reinterpret_cast<const float4*>(&asrc[u * 4]);
        #pragma unroll
        for (int t = 0; t < 4; t++) {
            const int task = warp + 8 * t;
            const int k0 = (task & 7) * 4;
            const int n0 = (task >> 3) * 32 + lane;
            const float* wp = W + (size_t)(c * 32 + k0) * DD + col0 + n0;
            wb[t].x = wp[0];
            wb[t].y = wp[DD];
            wb[t].z = wp[2 * DD];
            wb[t].w = wp[3 * DD];
        }
    };

    auto sts_chunk = [&](int bsel) {
        const uint32_t aoff = bsel ? GSM_A1 : GSM_A0;
        const uint32_t boff = bsel ? GSM_B1 : GSM_B0;
        const uint32_t rb = (uint32_t)(ar * 128 + acb * 4);
        #pragma unroll
        for (int u = 0; u < 4; u++) {
            uint4 t;
            t.x = f2tf32(xa[u].x); t.y = f2tf32(xa[u].y);
            t.z = f2tf32(xa[u].z); t.w = f2tf32(xa[u].w);
            *reinterpret_cast<uint4*>(smg + aoff + SWZ(rb + u * 16)) = t;
        }
        #pragma unroll
        for (int t = 0; t < 4; t++) {
            const int task = warp + 8 * t;
            const int k0 = (task & 7) * 4;
            const int n0 = (task >> 3) * 32 + lane;
            uint4 tt;
            tt.x = f2tf32(wb[t].x); tt.y = f2tf32(wb[t].y);
            tt.z = f2tf32(wb[t].z); tt.w = f2tf32(wb[t].w);
            *reinterpret_cast<uint4*>(smg + boff + SWZ(n0 * 128 + k0 * 4)) = tt;
        }
    };

    int ph0 = 0, ph1 = 0;

    ldg_chunk(0);   // prologue: chunk 0 into registers

    for (int c = 0; c < NCHUNK; c++) {
        const int buf = c & 1;

        if (c >= 2) {   // mma of chunk c-2 (same buffer) must be done
            if (buf == 0) { mbar_wait(mbar0, ph0); ph0 ^= 1; }
            else          { mbar_wait(mbar1, ph1); ph1 ^= 1; }
        }

        sts_chunk(buf);                 // store chunk c from registers
        if (c < NCHUNK - 1) ldg_chunk(c + 1);   // prefetch next (latency hidden)

        FENCE_ASYNC();
        __syncthreads();

        if (tid == 0) {
            const uint32_t aoff = buf ? GSM_A1 : GSM_A0;
            const uint32_t boff = buf ? GSM_B1 : GSM_B0;
            uint64_t ad = MAKE_DESC(smem_base + aoff);
            uint64_t bd = MAKE_DESC(smem_base + boff);
            #pragma unroll
            for (int s = 0; s < 4; s++)
                tcgen05_mma_tf32_ss(tmem, ad + s * 2, bd + s * 2,
                                    (c > 0 || s > 0) ? 1u : 0u);
            TC_COMMIT(buf == 0 ? mbar0 : mbar1);
        }
    }

    mbar_wait(mbar0, ph0);
    mbar_wait(mbar1, ph1);
    __syncthreads();

    if (warp < 4) {
        TC_FENCE_AFTER();
        const int row = row0 + warp * 32 + lane;
        const int b_ = row >> 11;
        const int s_ = row & 2047;
        float* obase = out + (size_t)(b_ * HH) * SS * HD + (size_t)s_ * HD;
        #pragma unroll
        for (int nb = 0; nb < 4; nb++) {
            uint32_t d_regs[32];
            TC_LD_X32(d_regs, tmem + nb * 32);
            TC_WAIT_LD();
            #pragma unroll
            for (int c4 = 0; c4 < 8; c4++) {
                const int col = col0 + nb * 32 + c4 * 4;
                const int h_ = col >> 6;
                const int d_ = col & 63;
                float4 bb = *reinterpret_cast<const float4*>(&bias[col]);
                float4 r;
                r.x = __uint_as_float(d_regs[c4 * 4 + 0]) + bb.x;
                r.y = __uint_as_float(d_regs[c4 * 4 + 1]) + bb.y;
                r.z = __uint_as_float(d_regs[c4 * 4 + 2]) + bb.z;
                r.w = __uint_as_float(d_regs[c4 * 4 + 3]) + bb.w;
                *reinterpret_cast<float4*>(&obase[(size_t)h_ * SS * HD + d_]) = r;
            }
        }
    }
    __syncthreads();
    if (warp == 0) TC_DEALLOC(tmem, TMEM_COLS);

#else
    // mma.sync fallback (R6, proven)
    uint32_t* As = reinterpret_cast<uint32_t*>(smg);
    uint32_t* Bs = As + 2 * 16 * LDW;

    const int wm = (warp & 1) * 64;
    const int wn = (warp >> 1) * 32;
    const int tig = lane & 3;
    const int grp = lane >> 2;

    float c[4][4][4];
    #pragma unroll
    for (int mt = 0; mt < 4; mt++)
        #pragma unroll
        for (int nt = 0; nt < 4; nt++)
            #pragma unroll
            for (int r = 0; r < 4; r++) c[mt][nt][r] = 0.f;

    float4 xa[2], wv[2];

    #pragma unroll
    for (int i = 0; i < 2; i++) {
        int idx = tid + i * 256;
        int arr = idx >> 2, akq = (idx & 3) * 4;
        xa[i] = *reinterpret_cast<const float4*>(&x[(size_t)(row0 + arr) * DD + akq]);
        int bkk = idx >> 5, bcc = (idx & 31) * 4;
        wv[i] = *reinterpret_cast<const float4*>(&W[(size_t)bkk * DD + col0 + bcc]);
    }
    #pragma unroll
    for (int i = 0; i < 2; i++) {
        int idx = tid + i * 256;
        int arr = idx >> 2, akq = (idx & 3) * 4;
        As[(akq + 0) * LDW + arr] = f2tf32(xa[i].x);
        As[(akq + 1) * LDW + arr] = f2tf32(xa[i].y);
        As[(akq + 2) * LDW + arr] = f2tf32(xa[i].z);
        As[(akq + 3) * LDW + arr] = f2tf32(xa[i].w);
        int bkk = idx >> 5, bcc = (idx & 31) * 4;
        uint4 wt2;
        wt2.x = f2tf32(wv[i].x); wt2.y = f2tf32(wv[i].y);
        wt2.z = f2tf32(wv[i].z); wt2.w = f2tf32(wv[i].w);
        *reinterpret_cast<uint4*>(&Bs[bkk * LDW + bcc]) = wt2;
    }
    __syncthreads();

    for (int kt = 0; kt < 64; kt++) {
        const int buf = kt & 1;
        uint32_t* Ab = As + buf * 16 * LDW;
        uint32_t* Bb = Bs + buf * 16 * LDW;

        if (kt < 63) {
            const int k0 = (kt + 1) * 16;
            #pragma unroll
            for (int i = 0; i < 2; i++) {
                int idx = tid + i * 256;
                int arr = idx >> 2, akq = (idx & 3) * 4;
                xa[i] = *reinterpret_cast<const float4*>(
                    &x[(size_t)(row0 + arr) * DD + k0 + akq]);
                int bkk = idx >> 5, bcc = (idx & 31) * 4;
                wv[i] = *reinterpret_cast<const float4*>(
                    &W[(size_t)(k0 + bkk) * DD + col0 + bcc]);
            }
        }

        #pragma unroll
        for (int ks = 0; ks < 16; ks += 8) {
            const int ak = ks + tig;
            uint32_t a[4][4], b[4][2];
            #pragma unroll
            for (int mt = 0; mt < 4; mt++) {
                int r = wm + mt * 16 + grp;
                a[mt][0] = Ab[ak * LDW + r];
                a[mt][1] = Ab[ak * LDW + r + 8];
                a[mt][2] = Ab[(ak + 4) * LDW + r];
                a[mt][3] = Ab[(ak + 4) * LDW + r + 8];
            }
            #pragma unroll
            for (int nt = 0; nt < 4; nt++) {
                int n = wn + nt * 8 + grp;
                b[nt][0] = Bb[ak * LDW + n];
                b[nt][1] = Bb[(ak + 4) * LDW + n];
            }
            #pragma unroll
            for (int mt = 0; mt < 4; mt++)
                #pragma unroll
                for (int nt = 0; nt < 4; nt++)
                    mma_tf32(c[mt][nt], a[mt], b[nt]);
        }

        if (kt < 63) {
            const int nb = buf ^ 1;
            uint32_t* An = As + nb * 16 * LDW;
            uint32_t* Bn = Bs + nb * 16 * LDW;
            #pragma unroll
            for (int i = 0; i < 2; i++) {
                int idx = tid + i * 256;
                int arr = idx >> 2, akq = (idx & 3) * 4;
                An[(akq + 0) * LDW + arr] = f2tf32(xa[i].x);
                An[(akq + 1) * LDW + arr] = f2tf32(xa[i].y);
                An[(akq + 2) * LDW + arr] = f2tf32(xa[i].z);
                An[(akq + 3) * LDW + arr] = f2tf32(xa[i].w);
                int bkk = idx >> 5, bcc = (idx & 31) * 4;
                uint4 wt2;
                wt2.x = f2tf32(wv[i].x); wt2.y = f2tf32(wv[i].y);
                wt2.z = f2tf32(wv[i].z); wt2.w = f2tf32(wv[i].w);
                *reinterpret_cast<uint4*>(&Bn[bkk * LDW + bcc]) = wt2;
            }
        }
        __syncthreads();
    }

    #pragma unroll
    for (int nt = 0; nt < 4; nt++) {
        const int col = col0 + wn + nt * 8 + tig * 2;
        const int h_ = col >> 6;
        const int d_ = col & 63;
        const float2 bb = *reinterpret_cast<const float2*>(&bias[col]);
        #pragma unroll
        for (int mt = 0; mt < 4; mt++) {
            int rowa = row0 + wm + mt * 16 + grp;
            #pragma unroll
            for (int half = 0; half < 2; half++) {
                int row = rowa + half * 8;
                int b_ = row >> 11;
                int s_ = row & 2047;
                float2 rv;
                rv.x = c[mt][nt][half * 2 + 0] + bb.x;
                rv.y = c[mt][nt][half * 2 + 1] + bb.y;
                *reinterpret_cast<float2*>(
                    &out[((size_t)((b_ * HH + h_) * SS) + s_) * HD + d_]) = rv;
            }
        }
    }
#endif
}

// ---------------------------------------------------------------------------
// tf32-mma flash block-sparse attention (R13, unchanged).
// ---------------------------------------------------------------------------
#define PADK 68
#define PADV 72
#define A_K0 0
#define A_K1 (64*PADK)
#define A_V0 (2*64*PADK)
#define A_V1 (2*64*PADK + 64*PADV)
#define A_KPM (2*64*PADK + 2*64*PADV)
#define A_FLOATS (A_KPM + 128)

__global__ void __launch_bounds__(128, 3)
sparse_attn_kernel(const float* __restrict__ kpm, float* __restrict__ out) {
    extern __shared__ float smf[];
    const uint32_t smem_base = smem_u32(smf);

    const int w = 31 - blockIdx.x;
    const int h = blockIdx.y;
    const int b = blockIdx.z;

    const int tid  = threadIdx.x;
    const int lane = tid & 31;
    const int warp = tid >> 5;
    const int wq   = warp * 16;
    const int grp  = lane >> 2;
    const int tig  = lane & 3;

    const size_t head_base = (size_t)(b * HH + h) * SS * HD;
    const int row_a = wq + grp;
    const int row_b = wq + grp + 8;
    const int nkt = (w + 3) >> 2;

    auto stage_tile = [&](int it, int bsel) {
        const uint32_t kbase = smem_base + (bsel ? A_K1 : A_K0) * 4;
        const uint32_t vbase = smem_base + (bsel ? A_V1 : A_V0) * 4;
        const bool isWinT = (it == nkt);
        #pragma unroll
        for (int j = 0; j < 8; j++) {
            int cch = tid + 128 * j;
            int r = cch >> 4;
            int c4 = (cch & 15) * 4;
            int sub = r >> 4, rr = r & 15;
            int kb, vsz;
            if (isWinT) { kb = 4 * w + sub; vsz = 16; }
            else {
                int g = it * 4 + sub;
                kb = (g < w) ? 4 * g + 3 : 3;
                vsz = (g < w) ? 16 : 0;
            }
            const float* ks = g_k + head_base + (size_t)(kb * 16 + rr) * HD + c4;
            const float* vs = g_v + head_base + (size_t)(kb * 16 + rr) * HD + c4;
            cp16(kbase + (uint32_t)(r * PADK + c4) * 4, ks, vsz);
            cp16(vbase + (uint32_t)(r * PADV + c4) * 4, vs, vsz);
        }
    };

    auto convert_tile = [&](int bsel) {
        float* Kb = smf + (bsel ? A_K1 : A_K0);
        float* Vb = smf + (bsel ? A_V1 : A_V0);
        #pragma unroll
        for (int j = 0; j < 8; j++) {
            int cch = tid + 128 * j;
            int r = cch >> 4;
            int c4 = (cch & 15) * 4;
            float4 kv = *reinterpret_cast<const float4*>(&Kb[r * PADK + c4]);
            uint4 kt;
            kt.x = f2tf32(kv.x); kt.y = f2tf32(kv.y);
            kt.z = f2tf32(kv.z); kt.w = f2tf32(kv.w);
            *reinterpret_cast<uint4*>(&Kb[r * PADK + c4]) = kt;
            float4 vv = *reinterpret_cast<const float4*>(&Vb[r * PADV + c4]);
            uint4 vt;
            vt.x = f2tf32(vv.x); vt.y = f2tf32(vv.y);
            vt.z = f2tf32(vv.z); vt.w = f2tf32(vv.w);
            *reinterpret_cast<uint4*>(&Vb[r * PADV + c4]) = vt;
        }
    };

    auto kpm_load = [&](int it) -> float {
        if (tid >= 64) return 0.f;
        const bool isWinT = (it == nkt);
        int kb; bool v2;
        if (isWinT) { kb = 4 * w + (tid >> 4); v2 = true; }
        else {
            int g = it * 4 + (tid >> 4);
            v2 = (g < w);
            kb = 4 * g + 3;
        }
        return v2 ? kpm[b * SS + kb * 16 + (tid & 15)] : -INFINITY;
    };

    uint32_t qa[8][4];
    {
        const float* qra = g_q + head_base + (size_t)(w * 64 + row_a) * HD;
        const float* qrb = g_q + head_base + (size_t)(w * 64 + row_b) * HD;
        #pragma unroll
        for (int ks = 0; ks < 8; ks++) {
            qa[ks][0] = f2tf32(qra[ks * 8 + tig]);
            qa[ks][1] = f2tf32(qrb[ks * 8 + tig]);
            qa[ks][2] = f2tf32(qra[ks * 8 + tig + 4]);
            qa[ks][3] = f2tf32(qrb[ks * 8 + tig + 4]);
        }
    }

    float o[8][4];
    #pragma unroll
    for (int nt = 0; nt < 8; nt++)
        #pragma unroll
        for (int r = 0; r < 4; r++) o[nt][r] = 0.f;
    float m0 = -1e30f, m1 = -1e30f, l0 = 0.f, l1 = 0.f;
    const float scale = 0.125f;

    stage_tile(0, 0);
    CP_COMMIT();
    float kpm_reg = kpm_load(0);

    for (int it = 0; it <= nkt; it++) {
        const int buf = it & 1;
        const uint32_t* Kb = reinterpret_cast<const uint32_t*>(smf + (buf ? A_K1 : A_K0));
        const uint32_t* Vb = reinterpret_cast<const uint32_t*>(smf + (buf ? A_V1 : A_V0));
        float* kpms = smf + A_KPM + buf * 64;
        const bool isWin = (it == nkt);

        CP_WAIT0();
        convert_tile(buf);
        if (tid < 64) kpms[tid] = kpm_reg;
        __syncthreads();

        if (it < nkt) {
            stage_tile(it + 1, buf ^ 1);
            CP_COMMIT();
            kpm_reg = kpm_load(it + 1);
        }

        float sc[8][4];
        #pragma unroll
        for (int nt = 0; nt < 8; nt++)
            #pragma unroll
            for (int r = 0; r < 4; r++) sc[nt][r] = 0.f;

        #pragma unroll
        for (int ks = 0; ks < 8; ks++) {
            #pragma unroll
            for (int nt = 0; nt < 8; nt++) {
                uint32_t bfr[2];
                bfr[0] = Kb[(nt * 8 + grp) * PADK + ks * 8 + tig];
                bfr[1] = Kb[(nt * 8 + grp) * PADK + ks * 8 + tig + 4];
                mma_tf32(sc[nt], qa[ks], bfr);
            }
        }

        #pragma unroll
        for (int nt = 0; nt < 8; nt++) {
            #pragma unroll
            for (int cc = 0; cc < 2; cc++) {
                int col = nt * 8 + tig * 2 + cc;
                float kv = kpms[col];
                float v0 = sc[nt][cc]     * scale + kv;
                float v1 = sc[nt][2 + cc] * scale + kv;
                if (isWin) {
                    if ((col >> 4) > (row_a >> 4)) v0 = -INFINITY;
                    if ((col >> 4) > (row_b >> 4)) v1 = -INFINITY;
                }
                sc[nt][cc] = v0;
                sc[nt][2 + cc] = v1;
            }
        }

        float mx0 = -INFINITY, mx1 = -INFINITY;
        #pragma unroll
        for (int nt = 0; nt < 8; nt++) {
            mx0 = fmaxf(mx0, fmaxf(sc[nt][0], sc[nt][1]));
            mx1 = fmaxf(mx1, fmaxf(sc[nt][2], sc[nt][3]));
        }
        mx0 = fmaxf(mx0, __shfl_xor_sync(0xffffffffu, mx0, 1));
        mx0 = fmaxf(mx0, __shfl_xor_sync(0xffffffffu, mx0, 2));
        mx1 = fmaxf(mx1, __shfl_xor_sync(0xffffffffu, mx1, 1));
        mx1 = fmaxf(mx1, __shfl_xor_sync(0xffffffffu, mx1, 2));

        const float nm0 = fmaxf(m0, mx0);
        const float nm1 = fmaxf(m1, mx1);
        const float al0 = __expf(m0 - nm0);
        const float al1 = __expf(m1 - nm1);
        m0 = nm0; m1 = nm1;

        float rs0 = 0.f, rs1 = 0.f;
        #pragma unroll
        for (int nt = 0; nt < 8; nt++) {
            #pragma unroll
            for (int cc = 0; cc < 2; cc++) {
                float p0 = __expf(sc[nt][cc] - nm0);
                float p1 = __expf(sc[nt][2 + cc] - nm1);
                sc[nt][cc] = p0;
                sc[nt][2 + cc] = p1;
                rs0 += p0; rs1 += p1;
            }
        }
        rs0 += __shfl_xor_sync(0xffffffffu, rs0, 1);
        rs0 += __shfl_xor_sync(0xffffffffu, rs0, 2);
        rs1 += __shfl_xor_sync(0xffffffffu, rs1, 1);
        rs1 += __shfl_xor_sync(0xffffffffu, rs1, 2);
        l0 = l0 * al0 + rs0;
        l1 = l1 * al1 + rs1;
        #pragma unroll
        for (int nt = 0; nt < 8; nt++) {
            o[nt][0] *= al0; o[nt][1] *= al0;
            o[nt][2] *= al1; o[nt][3] *= al1;
        }

        __syncthreads();

        uint32_t* Pb = const_cast<uint32_t*>(Kb);
        #pragma unroll
        for (int nt = 0; nt < 8; nt++) {
            uint2 p0, p1;
            p0.x = f2tf32(sc[nt][0]); p0.y = f2tf32(sc[nt][1]);
            p1.x = f2tf32(sc[nt][2]); p1.y = f2tf32(sc[nt][3]);
            *reinterpret_cast<uint2*>(&Pb[row_a * PADK + nt * 8 + tig * 2]) = p0;
            *reinterpret_cast<uint2*>(&Pb[row_b * PADK + nt * 8 + tig * 2]) = p1;
        }
        __syncwarp();

        #pragma unroll
        for (int ks = 0; ks < 8; ks++) {
            uint32_t a[4];
            a[0] = Pb[row_a * PADK + ks * 8 + tig];
            a[1] = Pb[row_b * PADK + ks * 8 + tig];
            a[2] = Pb[row_a * PADK + ks * 8 + tig + 4];
            a[3] = Pb[row_b * PADK + ks * 8 + tig + 4];
            #pragma unroll
            for (int nt = 0; nt < 8; nt++) {
                uint32_t bfr[2];
                bfr[0] = Vb[(ks * 8 + tig) * PADV + nt * 8 + grp];
                bfr[1] = Vb[(ks * 8 + tig + 4) * PADV + nt * 8 + grp];
                mma_tf32(o[nt], a, bfr);
            }
        }
    }

    const float inv0 = 1.f / l0;
    const float inv1 = 1.f / l1;
    #pragma unroll
    for (int nt = 0; nt < 8; nt++) {
        int d_ = nt * 8 + tig * 2;
        float2 r0, r1;
        r0.x = o[nt][0] * inv0; r0.y = o[nt][1] * inv0;
        r1.x = o[nt][2] * inv1; r1.y = o[nt][3] * inv1;
        *reinterpret_cast<float2*>(
            &out[(size_t)(b * SS + w * 64 + row_a) * DD + h * HD + d_]) = r0;
        *reinterpret_cast<float2*>(
            &out[(size_t)(b * SS + w * 64 + row_b) * DD + h * HD + d_]) = r1;
    }
}

// ---------------------------------------------------------------------------
// Launch
// ---------------------------------------------------------------------------
extern "C" void kernel_launch(void* const* d_in, const int* in_sizes, int n_in,
                              void* d_out, int out_size) {
    const float* x   = (const float*)d_in[0];
    const float* kpm = (const float*)d_in[1];
    const float* Wq  = (const float*)d_in[2];
    const float* bq  = (const float*)d_in[3];
    const float* Wk  = (const float*)d_in[4];
    const float* bk  = (const float*)d_in[5];
    const float* Wv  = (const float*)d_in[6];
    const float* bv  = (const float*)d_in[7];
    float* out = (float*)d_out;

    static int smem_set = 0;
    const int attn_smem = A_FLOATS * sizeof(float);   // 72192
    if (!smem_set) {
        cudaFuncSetAttribute(sparse_attn_kernel,
                             cudaFuncAttributeMaxDynamicSharedMemorySize,
                             attn_smem);
        cudaFuncSetAttribute(qkv_gemm_tc,
                             cudaFuncAttributeMaxDynamicSharedMemorySize,
                             GSM_TOTAL);
        smem_set = 1;
    }

    dim3 ggrid(32, 8);
    qkv_gemm_tc<<<ggrid, 256, GSM_TOTAL>>>(x, Wq, bq, 0);
    qkv_gemm_tc<<<ggrid, 256, GSM_TOTAL>>>(x, Wk, bk, 1);
    qkv_gemm_tc<<<ggrid, 256, GSM_TOTAL>>>(x, Wv, bv, 2);

    dim3 agrid(32, HH, BB);
    sparse_attn_kernel<<<agrid, 128, attn_smem>>>(kpm, out);
}